// round 16
// baseline (speedup 1.0000x reference)
#include <cuda_runtime.h>

// Closed-form normalization constants.
#define Y00f  0.28209479177387814f    // 1/(2*sqrt(pi))
#define N10f  0.48860251190291992f    // sqrt(3/(4pi))
#define N20f  0.63078313050504001f    // sqrt(5/(4pi))
#define C21f  (-1.09254843059207907f) // -(1/2)*sqrt(15/pi)
#define C22f  0.54627421529603953f    // (1/4)*sqrt(15/pi)
#define K20f  0.35355339059327379f    // 1/(2*sqrt(2))
#define K21f  0.20412414523193152f    // 1/(2*sqrt(6))
#define K30f  0.06415002990995843f    // 1/(9*sqrt(3))
#define K31f  0.04536092116208279f    // sqrt(1/486)
#define K32f  0.02028602047074832f    // sqrt(8/19440)

typedef unsigned long long u64;

__device__ __forceinline__ u64 pk(float lo, float hi) {
    u64 r; asm("mov.b64 %0,{%1,%2};" : "=l"(r) : "f"(lo), "f"(hi)); return r;
}
__device__ __forceinline__ void upk(u64 v, float& lo, float& hi) {
    asm("mov.b64 {%0,%1},%2;" : "=f"(lo), "=f"(hi) : "l"(v));
}
__device__ __forceinline__ u64 f2mul(u64 a, u64 b) {
    u64 d; asm("mul.rn.f32x2 %0,%1,%2;" : "=l"(d) : "l"(a), "l"(b)); return d;
}
__device__ __forceinline__ u64 f2fma(u64 a, u64 b, u64 c) {
    u64 d; asm("fma.rn.f32x2 %0,%1,%2,%3;" : "=l"(d) : "l"(a), "l"(b), "l"(c)); return d;
}
__device__ __forceinline__ u64 f2add(u64 a, u64 b) {
    u64 d; asm("add.rn.f32x2 %0,%1,%2;" : "=l"(d) : "l"(a), "l"(b)); return d;
}

// L2 evict_last policy via cache_hint form (validated in R15: +0.6us ncu win).
__device__ __forceinline__ u64 mkpolicy_evict_last() {
    u64 pol;
    asm("createpolicy.fractional.L2::evict_last.b64 %0, 1.0;" : "=l"(pol));
    return pol;
}
__device__ __forceinline__ float4 ldg_el(const float4* p, u64 pol) {
    float4 v;
    asm volatile("ld.global.nc.L2::cache_hint.v4.f32 {%0,%1,%2,%3}, [%4], %5;"
                 : "=f"(v.x), "=f"(v.y), "=f"(v.z), "=f"(v.w)
                 : "l"(p), "l"(pol));
    return v;
}

// 15 packed coefficient registers (lo == hi) + 1 scalar (b5s).
struct Co {
    u64 b0, b1n, b1d;
    u64 a2, a3, a4;
    u64 a6, a7, a8;
    u64 w9a, cw, w10, w11, w12m, w13;
    float b5s;
};

// Per-point prep: MUFU + imm-FFMA only.
struct P8 { float r, t, ct, st, cp, sp, l30b, g3c; };

__device__ __forceinline__ P8 prep(float r, float th, float ph, float b5s) {
    P8 p;
    p.r = r;
    __sincosf(th, &p.st, &p.ct);
    __sincosf(ph, &p.sp, &p.cp);
    p.t = __expf(r * (-1.0f / 6.0f));               // e^{-r/6}
    float u = fmaf(r, 4.0f / 9.0f, -4.0f);
    p.l30b = fmaf(u, r, 6.0f) * b5s;                // b5*((4/9)r^2-4r+6)
    p.g3c  = fmaf(r, -4.0f / 9.0f, 8.0f / 3.0f);    // (8/3)-(4/9)r
    return p;
}

// Lean fully packed evaluation of two points (validated R7).
__device__ __forceinline__ u64 eval_pair(const P8& p0, const P8& p1, const Co& C) {
    u64 R   = pk(p0.r,    p1.r),    T   = pk(p0.t,   p1.t);
    u64 CT  = pk(p0.ct,   p1.ct),   ST  = pk(p0.st,  p1.st);
    u64 CP  = pk(p0.cp,   p1.cp),   SP  = pk(p0.sp,  p1.sp);
    u64 L30B = pk(p0.l30b, p1.l30b), G3C = pk(p0.g3c, p1.g3c);

    u64 T2 = f2mul(T, T), T3 = f2mul(T2, T), T6 = f2mul(T3, T3);
    u64 R2 = f2mul(R, R);
    u64 SPSP = f2mul(SP, SP), SPCP = f2mul(SP, CP);
    u64 CTCT = f2mul(CT, CT), ST2 = f2mul(ST, ST), CTST = f2mul(CT, ST);

    u64 X1 = f2fma(CT, C.a2, f2mul(ST, f2fma(CP, C.a3, f2mul(SP, C.a4))));
    u64 B3 = f2fma(R, f2add(X1, C.b1n), C.b1d);

    u64 X2 = f2fma(CT, C.a6, f2mul(ST, f2fma(CP, C.a7, f2mul(SP, C.a8))));
    u64 G3 = f2mul(R, G3C);
    u64 P2 = f2fma(G3, X2, L30B);

    u64 Y = f2fma(CP, C.w10, f2mul(SP, C.w11));
    u64 Z = f2fma(SPCP, C.w13, f2mul(SPSP, C.w12m));
    u64 W = f2fma(ST2, Z, f2fma(CTST, Y, f2fma(CTCT, C.w9a, C.cw)));
    u64 B2 = f2fma(R2, W, P2);

    return f2fma(T6, C.b0, f2fma(T3, B3, f2mul(T2, B2)));
}

__global__ __launch_bounds__(128)
void orbital_eval_kernel(const float* __restrict__ pos,
                         const float* __restrict__ coeffs,
                         float* __restrict__ out,
                         int n4, int n) {
    int tid0   = blockIdx.x * blockDim.x + threadIdx.x;
    int stride = gridDim.x * blockDim.x;

    // Per-thread coefficient fold, amortized over the grid-stride loop.
    float c[14];
#pragma unroll
    for (int k = 0; k < 14; k++) c[k] = __ldg(&coeffs[k]);

    Co C;
    {
        float b0  =  2.0f * Y00f * c[0];
        float b1  =  Y00f * K20f * c[1];
        float a2  =  N10f * K21f * c[3];
        float a3  = -N10f * K21f * c[4];
        float a4  = -N10f * K21f * c[2];
        float a6  =  N10f * K31f * c[7];
        float a7  = -N10f * K31f * c[8];
        float a8  = -N10f * K31f * c[6];
        float n2  =  N20f * K32f * c[11];
        float q12 =  (4.0f / 9.0f) * C21f * K32f * c[12];
        float q10 =  (4.0f / 9.0f) * C21f * K32f * c[10];
        float e13 =  (4.0f / 9.0f) * C22f * K32f * c[13];
        float e9  =  (8.0f / 9.0f) * C22f * K32f * c[9];
        float w9a = (2.0f / 3.0f) * n2 - e13;
        float cw  = -(2.0f / 9.0f) * n2 + e13;
        C.b0  = pk(b0, b0);
        C.b1n = pk(-b1, -b1);
        C.b1d = pk(2.0f * b1, 2.0f * b1);
        C.a2 = pk(a2, a2); C.a3 = pk(a3, a3); C.a4 = pk(a4, a4);
        C.a6 = pk(a6, a6); C.a7 = pk(a7, a7); C.a8 = pk(a8, a8);
        C.w9a = pk(w9a, w9a); C.cw = pk(cw, cw);
        C.w10 = pk(q12, q12); C.w11 = pk(q10, q10);
        C.w12m = pk(-2.0f * e13, -2.0f * e13); C.w13 = pk(e9, e9);
        C.b5s = Y00f * K30f * c[5];
    }

    u64 pol = mkpolicy_evict_last();
    const float4* p4 = reinterpret_cast<const float4*>(pos);
    float4* o4       = reinterpret_cast<float4*>(out);

    int i = tid0;
    if (i < n4) {
        // Prologue: first iteration's loads (evict_last — pin in L2).
        float4 v0 = ldg_el(&p4[3 * i + 0], pol);
        float4 v1 = ldg_el(&p4[3 * i + 1], pol);
        float4 v2 = ldg_el(&p4[3 * i + 2], pol);

        while (true) {
            // Prefetch next iteration before computing current one.
            int j = i + stride;
            bool have = (j < n4);
            float4 w0, w1, w2;
            if (have) {
                w0 = ldg_el(&p4[3 * j + 0], pol);
                w1 = ldg_el(&p4[3 * j + 1], pol);
                w2 = ldg_el(&p4[3 * j + 2], pol);
            }

            P8 q0 = prep(v0.x, v0.y, v0.z, C.b5s);
            P8 q1 = prep(v0.w, v1.x, v1.y, C.b5s);
            u64 r01 = eval_pair(q0, q1, C);
            P8 q2 = prep(v1.z, v1.w, v2.x, C.b5s);
            P8 q3 = prep(v2.y, v2.z, v2.w, C.b5s);
            u64 r23 = eval_pair(q2, q3, C);

            float4 o;
            upk(r01, o.x, o.y);
            upk(r23, o.z, o.w);
            __stcs(&o4[i], o);   // streaming store (evict-first)

            if (!have) break;
            v0 = w0; v1 = w1; v2 = w2;
            i = j;
        }
    }

    // Scalar tail (n % 4 != 0).
    int tail = n - n4 * 4;
    if (tid0 < tail) {
        int idx = n4 * 4 + tid0;
        P8 p = prep(pos[3 * idx], pos[3 * idx + 1], pos[3 * idx + 2], C.b5s);
        u64 rr = eval_pair(p, p, C);
        float lo, hi; upk(rr, lo, hi);
        out[idx] = lo;
    }
}

extern "C" void kernel_launch(void* const* d_in, const int* in_sizes, int n_in,
                              void* d_out, int out_size) {
    const float* pos    = (const float*)d_in[0];   // (2048, 4096, 3) fp32
    const float* coeffs = (const float*)d_in[1];   // (14,) fp32
    float* out          = (float*)d_out;           // (2048, 4096) fp32

    int n  = out_size;
    int n4 = n / 4;

    const int threads = 128;
    const int iters   = 6;   // grid-stride iterations per thread
    long long groups  = (n4 > 0) ? n4 : 1;
    int blocks = (int)((groups + (long long)threads * iters - 1) / ((long long)threads * iters));
    if (blocks < 1) blocks = 1;

    orbital_eval_kernel<<<blocks, threads>>>(pos, coeffs, out, n4, n);
}